// round 4
// baseline (speedup 1.0000x reference)
#include <cuda_runtime.h>
#include <math.h>

// Problem constants (fixed shapes from reference)
#define BSZ 2
#define HWN 4096              // H*W
#define CD  512
#define NBROWS (BSZ*HWN)      // 8192
#define NGROUPS 32

// -------------------- scratch (device globals; no allocations) -------------
// g_xn is dead after the QKV projections; g_ao (attn@v result) aliases it.
__device__ float g_xn  [(size_t)NBROWS*CD];           // also used as "ao"
__device__ float g_qkv [(size_t)3*NBROWS*CD];         // q | k | v slabs
__device__ float g_attn[(size_t)BSZ*HWN*HWN];         // 134 MB
__device__ float g_mean[BSZ*NGROUPS];
__device__ float g_rstd[BSZ*NGROUPS];

// -------------------- GroupNorm: stats --------------------
// one block per (b,g); reduce 4096*16 = 65536 elements
__global__ void gn_stats(const float* __restrict__ x,
                         float* __restrict__ mean, float* __restrict__ rstd) {
    __shared__ float shs[8], shss[8];
    const int bg = blockIdx.x;
    const int b = bg >> 5, g = bg & 31;
    const float4* xb = (const float4*)x + (size_t)b*524288 + g*4;
    float s = 0.f, ss = 0.f;
    for (int i = threadIdx.x; i < 16384; i += 256) {
        int n = i >> 2, j = i & 3;
        float4 vv = xb[(size_t)n*128 + j];
        s  += vv.x + vv.y + vv.z + vv.w;
        ss += vv.x*vv.x + vv.y*vv.y + vv.z*vv.z + vv.w*vv.w;
    }
    #pragma unroll
    for (int o = 16; o; o >>= 1) {
        s  += __shfl_xor_sync(0xffffffffu, s,  o);
        ss += __shfl_xor_sync(0xffffffffu, ss, o);
    }
    if ((threadIdx.x & 31) == 0) { shs[threadIdx.x>>5] = s; shss[threadIdx.x>>5] = ss; }
    __syncthreads();
    if (threadIdx.x == 0) {
        s = 0.f; ss = 0.f;
        #pragma unroll
        for (int w = 0; w < 8; w++) { s += shs[w]; ss += shss[w]; }
        float m   = s * (1.f/65536.f);
        float var = ss * (1.f/65536.f) - m*m;
        mean[bg] = m;
        rstd[bg] = rsqrtf(var + 1e-5f);
    }
}

// -------------------- GroupNorm: normalize (coalesced float4) ---------------
__global__ void gn_norm(const float* __restrict__ x,
                        const float* __restrict__ gamma, const float* __restrict__ beta,
                        const float* __restrict__ mean, const float* __restrict__ rstd,
                        float* __restrict__ xn) {
    const int idx = blockIdx.x * blockDim.x + threadIdx.x;   // float4 index
    float4 v = ((const float4*)x)[idx];
    const int c4 = idx & 127;        // float4 index within channel dim (C/4 = 128)
    const int b  = idx >> 19;        // 4096*512/4 = 2^19 float4 per batch
    const int g  = c4 >> 2;          // (c4*4)/16
    const int bg = b * 32 + g;
    const float m = mean[bg], r = rstd[bg];
    const float4 ga = ((const float4*)gamma)[c4];
    const float4 be = ((const float4*)beta)[c4];
    float4 o;
    o.x = (v.x - m) * r * ga.x + be.x;
    o.y = (v.y - m) * r * ga.y + be.y;
    o.z = (v.z - m) * r * ga.z + be.z;
    o.w = (v.w - m) * r * ga.w + be.w;
    ((float4*)xn)[idx] = o;
}

// -------------------- Generic fp32 GEMM ------------------------------------
// C[M,N] = alpha * A[M,K] * op(B) (+ bias[N]) (+ res[M,N])
// TRANSB=false: B is [K,N] row-major.  TRANSB=true: B is [N,K] row-major (NT).
// 128x128 block tile, BK=16, 256 threads, 8x8 per thread (4+4 split layout).
template<bool TRANSB, bool BIAS, bool RES>
__global__ __launch_bounds__(256)
void gemm_kernel(const float* __restrict__ A, const float* __restrict__ Bm,
                 const float* __restrict__ bias, const float* __restrict__ res,
                 float* __restrict__ Cm, int M, int N, int K, float alpha) {
    __shared__ float As[16][128];
    __shared__ float Bs[16][128];

    const int tid = threadIdx.x;
    const int tx = tid & 15;
    const int ty = tid >> 4;
    const int rowBlock = blockIdx.y * 128;
    const int colBlock = blockIdx.x * 128;

    float acc[8][8];
    #pragma unroll
    for (int i = 0; i < 8; i++)
        #pragma unroll
        for (int j = 0; j < 8; j++) acc[i][j] = 0.f;

    for (int k0 = 0; k0 < K; k0 += 16) {
        // A tile: 128 rows x 16 k (transposed store into As[k][m])
        #pragma unroll
        for (int p = 0; p < 2; p++) {
            int t = tid + p * 256;
            int r = t >> 2;
            int c = (t & 3) << 2;
            const float4 va = *(const float4*)(A + (size_t)(rowBlock + r) * K + k0 + c);
            As[c+0][r] = va.x; As[c+1][r] = va.y; As[c+2][r] = va.z; As[c+3][r] = va.w;
        }
        if (TRANSB) {
            // B tile from [N,K]: rows are n, contiguous along k -> transpose into Bs[k][n]
            #pragma unroll
            for (int p = 0; p < 2; p++) {
                int t = tid + p * 256;
                int r = t >> 2;            // n within tile
                int c = (t & 3) << 2;      // k within tile
                const float4 vb = *(const float4*)(Bm + (size_t)(colBlock + r) * K + k0 + c);
                Bs[c+0][r] = vb.x; Bs[c+1][r] = vb.y; Bs[c+2][r] = vb.z; Bs[c+3][r] = vb.w;
            }
        } else {
            // B tile from [K,N]: straight float4 copy
            #pragma unroll
            for (int p = 0; p < 2; p++) {
                int t = tid + p * 256;
                int r = t >> 5;            // k row 0..15
                int c = (t & 31) << 2;     // col
                *(float4*)&Bs[r][c] =
                    *(const float4*)(Bm + (size_t)(k0 + r) * N + colBlock + c);
            }
        }
        __syncthreads();

        #pragma unroll
        for (int kk = 0; kk < 16; kk++) {
            float af[8], bf[8];
            *(float4*)&af[0] = *(const float4*)&As[kk][ty*4];
            *(float4*)&af[4] = *(const float4*)&As[kk][64 + ty*4];
            *(float4*)&bf[0] = *(const float4*)&Bs[kk][tx*4];
            *(float4*)&bf[4] = *(const float4*)&Bs[kk][64 + tx*4];
            #pragma unroll
            for (int i = 0; i < 8; i++)
                #pragma unroll
                for (int j = 0; j < 8; j++)
                    acc[i][j] += af[i] * bf[j];
        }
        __syncthreads();
    }

    // epilogue
    #pragma unroll
    for (int i = 0; i < 8; i++) {
        const int rl = (i < 4) ? (ty*4 + i) : (64 + ty*4 + (i - 4));
        const size_t r = (size_t)(rowBlock + rl);
        #pragma unroll
        for (int jh = 0; jh < 2; jh++) {
            const int cl = jh*64 + tx*4;
            const size_t c = (size_t)(colBlock + cl);
            float4 o;
            o.x = acc[i][jh*4+0] * alpha;
            o.y = acc[i][jh*4+1] * alpha;
            o.z = acc[i][jh*4+2] * alpha;
            o.w = acc[i][jh*4+3] * alpha;
            if (BIAS) {
                const float4 bb = *(const float4*)(bias + c);
                o.x += bb.x; o.y += bb.y; o.z += bb.z; o.w += bb.w;
            }
            if (RES) {
                const float4 rr = *(const float4*)(res + r * N + c);
                o.x += rr.x; o.y += rr.y; o.z += rr.z; o.w += rr.w;
            }
            *(float4*)(Cm + r * N + c) = o;
        }
    }
}

// -------------------- Row softmax (in-place), one block per row -------------
__global__ void softmax_kernel(float* __restrict__ S) {
    __shared__ float sh[8];
    const size_t row = blockIdx.x;
    float* p = S + row * 4096;
    const int tid = threadIdx.x;
    float4 v[4];
    float mx = -1e30f;
    #pragma unroll
    for (int i = 0; i < 4; i++) {
        v[i] = ((const float4*)p)[tid + i*256];
        mx = fmaxf(mx, fmaxf(fmaxf(v[i].x, v[i].y), fmaxf(v[i].z, v[i].w)));
    }
    #pragma unroll
    for (int o = 16; o; o >>= 1) mx = fmaxf(mx, __shfl_xor_sync(0xffffffffu, mx, o));
    if ((tid & 31) == 0) sh[tid >> 5] = mx;
    __syncthreads();
    mx = sh[0];
    #pragma unroll
    for (int w = 1; w < 8; w++) mx = fmaxf(mx, sh[w]);

    float sum = 0.f;
    #pragma unroll
    for (int i = 0; i < 4; i++) {
        v[i].x = expf(v[i].x - mx); v[i].y = expf(v[i].y - mx);
        v[i].z = expf(v[i].z - mx); v[i].w = expf(v[i].w - mx);
        sum += v[i].x + v[i].y + v[i].z + v[i].w;
    }
    #pragma unroll
    for (int o = 16; o; o >>= 1) sum += __shfl_xor_sync(0xffffffffu, sum, o);
    __syncthreads();                 // protect sh reuse
    if ((tid & 31) == 0) sh[tid >> 5] = sum;
    __syncthreads();
    sum = 0.f;
    #pragma unroll
    for (int w = 0; w < 8; w++) sum += sh[w];
    const float inv = 1.f / sum;
    #pragma unroll
    for (int i = 0; i < 4; i++) {
        v[i].x *= inv; v[i].y *= inv; v[i].z *= inv; v[i].w *= inv;
        ((float4*)p)[tid + i*256] = v[i];
    }
}

// -------------------- launch -----------------------------------------------
extern "C" void kernel_launch(void* const* d_in, const int* in_sizes, int n_in,
                              void* d_out, int out_size) {
    const float* x     = (const float*)d_in[0];
    const float* gamma = (const float*)d_in[1];
    const float* beta  = (const float*)d_in[2];
    const float* wq    = (const float*)d_in[3];
    const float* bq    = (const float*)d_in[4];
    const float* wk    = (const float*)d_in[5];
    const float* bk    = (const float*)d_in[6];
    const float* wv    = (const float*)d_in[7];
    const float* bv    = (const float*)d_in[8];
    const float* wp    = (const float*)d_in[9];
    const float* bp    = (const float*)d_in[10];
    float* out = (float*)d_out;

    float *xn, *qkv, *attn, *mean, *rstd;
    cudaGetSymbolAddress((void**)&xn,   g_xn);
    cudaGetSymbolAddress((void**)&qkv,  g_qkv);
    cudaGetSymbolAddress((void**)&attn, g_attn);
    cudaGetSymbolAddress((void**)&mean, g_mean);
    cudaGetSymbolAddress((void**)&rstd, g_rstd);
    float* q  = qkv;
    float* k  = qkv + (size_t)NBROWS*CD;
    float* v  = qkv + (size_t)2*NBROWS*CD;
    float* ao = xn;   // alias: xn dead after QKV projections

    // 1) GroupNorm
    gn_stats<<<BSZ*NGROUPS, 256>>>(x, mean, rstd);
    gn_norm<<<(NBROWS*CD/4)/256, 256>>>(x, gamma, beta, mean, rstd, xn);

    // 2) q, k, v projections (both batches stacked: [8192,512] x [512,512])
    const dim3 gProj(CD/128, NBROWS/128);
    gemm_kernel<false, true, false><<<gProj, 256>>>(xn, wq, bq, nullptr, q, NBROWS, CD, CD, 1.f);
    gemm_kernel<false, true, false><<<gProj, 256>>>(xn, wk, bk, nullptr, k, NBROWS, CD, CD, 1.f);
    gemm_kernel<false, true, false><<<gProj, 256>>>(xn, wv, bv, nullptr, v, NBROWS, CD, CD, 1.f);

    // 3) scores = q k^T * (1/sqrt(C)), per batch (NT GEMM)
    const float scale = 0.044194173824159216f;   // 1/sqrt(512)
    const dim3 gScore(HWN/128, HWN/128);
    for (int b = 0; b < BSZ; b++) {
        gemm_kernel<true, false, false><<<gScore, 256>>>(
            q + (size_t)b*HWN*CD, k + (size_t)b*HWN*CD, nullptr, nullptr,
            attn + (size_t)b*HWN*HWN, HWN, HWN, CD, scale);
    }

    // 4) softmax rows (in place)
    softmax_kernel<<<NBROWS, 256>>>(attn);

    // 5) out = attn @ v, per batch (ao aliases xn — xn is dead by now)
    const dim3 gAV(CD/128, HWN/128);
    for (int b = 0; b < BSZ; b++) {
        gemm_kernel<false, false, false><<<gAV, 256>>>(
            attn + (size_t)b*HWN*HWN, v + (size_t)b*HWN*CD, nullptr, nullptr,
            ao + (size_t)b*HWN*CD, HWN, CD, HWN, 1.f);
    }

    // 6) final projection + bias + residual -> d_out
    gemm_kernel<false, true, true><<<gProj, 256>>>(ao, wp, bp, x, out, NBROWS, CD, CD, 1.f);
}

// round 7
// speedup vs baseline: 2.5126x; 2.5126x over previous
#include <cuda_runtime.h>
#include <math.h>
#include <stdint.h>

// Problem constants (fixed shapes)
#define BSZ 2
#define HWN 4096
#define CD  512
#define NBROWS (BSZ*HWN)      // 8192
#define NGROUPS 32

// ---------------------------------------------------------------------------
// Scratch (device globals; no allocations)
// ---------------------------------------------------------------------------
__device__ float g_xn  [(size_t)NBROWS*CD];           // xn; later reused as "ao"
__device__ float g_qkv [(size_t)3*NBROWS*CD];         // q | k | v
__device__ float g_attn[(size_t)BSZ*HWN*HWN];         // 134 MB
__device__ float g_vt  [(size_t)BSZ*CD*HWN];          // v transposed per batch
__device__ float g_wt  [(size_t)4*CD*CD];             // wq^T | wk^T | wv^T | wp^T
__device__ float g_mean[BSZ*NGROUPS];
__device__ float g_rstd[BSZ*NGROUPS];

// ---------------------------------------------------------------------------
// tf32 helpers (portable sm_80+ path; NO 'a'-suffix features)
// ---------------------------------------------------------------------------
__device__ __forceinline__ uint32_t f2tf32(float f) {
    uint32_t u;
    asm("cvt.rna.tf32.f32 %0, %1;" : "=r"(u) : "f"(f));
    return u;
}
__device__ __forceinline__ void mma_tf32(float c[4], const uint32_t a[4], const uint32_t b[2]) {
    asm volatile(
        "mma.sync.aligned.m16n8k8.row.col.f32.tf32.tf32.f32 "
        "{%0,%1,%2,%3}, {%4,%5,%6,%7}, {%8,%9}, {%0,%1,%2,%3};"
        : "+f"(c[0]), "+f"(c[1]), "+f"(c[2]), "+f"(c[3])
        : "r"(a[0]), "r"(a[1]), "r"(a[2]), "r"(a[3]), "r"(b[0]), "r"(b[1]));
}

// ---------------------------------------------------------------------------
// GroupNorm
// ---------------------------------------------------------------------------
__global__ void gn_stats(const float* __restrict__ x,
                         float* __restrict__ mean, float* __restrict__ rstd) {
    __shared__ float shs[8], shss[8];
    const int bg = blockIdx.x;
    const int b = bg >> 5, g = bg & 31;
    const float4* xb = (const float4*)x + (size_t)b*524288 + g*4;
    float s = 0.f, ss = 0.f;
    for (int i = threadIdx.x; i < 16384; i += 256) {
        int n = i >> 2, j = i & 3;
        float4 vv = xb[(size_t)n*128 + j];
        s  += vv.x + vv.y + vv.z + vv.w;
        ss += vv.x*vv.x + vv.y*vv.y + vv.z*vv.z + vv.w*vv.w;
    }
    #pragma unroll
    for (int o = 16; o; o >>= 1) {
        s  += __shfl_xor_sync(0xffffffffu, s,  o);
        ss += __shfl_xor_sync(0xffffffffu, ss, o);
    }
    if ((threadIdx.x & 31) == 0) { shs[threadIdx.x>>5] = s; shss[threadIdx.x>>5] = ss; }
    __syncthreads();
    if (threadIdx.x == 0) {
        s = 0.f; ss = 0.f;
        #pragma unroll
        for (int w = 0; w < 8; w++) { s += shs[w]; ss += shss[w]; }
        float m   = s * (1.f/65536.f);
        float var = ss * (1.f/65536.f) - m*m;
        mean[bg] = m;
        rstd[bg] = rsqrtf(var + 1e-5f);
    }
}

__global__ void gn_norm(const float* __restrict__ x,
                        const float* __restrict__ gamma, const float* __restrict__ beta,
                        const float* __restrict__ mean, const float* __restrict__ rstd,
                        float* __restrict__ xn) {
    const int idx = blockIdx.x * blockDim.x + threadIdx.x;
    float4 v = ((const float4*)x)[idx];
    const int c4 = idx & 127;
    const int b  = idx >> 19;
    const int g  = c4 >> 2;
    const int bg = b * 32 + g;
    const float m = mean[bg], r = rstd[bg];
    const float4 ga = ((const float4*)gamma)[c4];
    const float4 be = ((const float4*)beta)[c4];
    float4 o;
    o.x = (v.x - m) * r * ga.x + be.x;
    o.y = (v.y - m) * r * ga.y + be.y;
    o.z = (v.z - m) * r * ga.z + be.z;
    o.w = (v.w - m) * r * ga.w + be.w;
    ((float4*)xn)[idx] = o;
}

// ---------------------------------------------------------------------------
// Tiled transpose: out[c][r] = in[r][c].  block (32,8), grid (cols/32, rows/32, nz)
// ---------------------------------------------------------------------------
__global__ void transpose_kernel(const float* __restrict__ in, float* __restrict__ out,
                                 int rows, int cols, size_t zInStride, size_t zOutStride) {
    __shared__ float t[32][33];
    const float* inz = in + blockIdx.z * zInStride;
    float* outz = out + blockIdx.z * zOutStride;
    int c0 = blockIdx.x * 32, r0 = blockIdx.y * 32;
    int x = threadIdx.x;
    #pragma unroll
    for (int y = threadIdx.y; y < 32; y += 8)
        t[y][x] = inz[(size_t)(r0 + y) * cols + c0 + x];
    __syncthreads();
    #pragma unroll
    for (int y = threadIdx.y; y < 32; y += 8)
        outz[(size_t)(c0 + y) * rows + r0 + x] = t[x][y];
}

// ---------------------------------------------------------------------------
// Tensor-core tf32 NT GEMM:
//   Cm[m][n] = alpha * sum_k A[m][k] * Bt[n][k]  (+bias[n]) (+res[m][n])
// CTA tile 128x128, BK=16, 256 threads = 8 warps in 2(m) x 4(n), warp tile 64x32.
// SMEM k-major with +4 float pad (stride 20) -> conflict-free fragment loads.
// blockIdx.z selects batch via zA/zB/zC element strides.
// ---------------------------------------------------------------------------
#define SMS 20   // smem row stride in 32-bit words

template<bool BIAS, bool RES>
__global__ __launch_bounds__(256)
void gemm_mma(const float* __restrict__ A, const float* __restrict__ Bt,
              const float* __restrict__ bias, const float* __restrict__ res,
              float* __restrict__ Cm,
              int K, int lda, int ldb, int ldc, float alpha,
              size_t zA, size_t zB, size_t zC) {
    __shared__ uint32_t As[128 * SMS];
    __shared__ uint32_t Bs[128 * SMS];

    A  += blockIdx.z * zA;
    Bt += blockIdx.z * zB;
    Cm += blockIdx.z * zC;
    const float* resz = RES ? (res + blockIdx.z * zC) : res;

    const int tid = threadIdx.x;
    const int wid = tid >> 5;
    const int lane = tid & 31;
    const int gid = lane >> 2;        // 0..7
    const int tg  = lane & 3;         // 0..3
    const int wm = (wid & 1) * 64;    // warp m offset
    const int wn = (wid >> 1) * 32;   // warp n offset
    const int rowBlock = blockIdx.y * 128;
    const int colBlock = blockIdx.x * 128;

    // ld row/col for global->smem stage: each thread does 2 rows' quarters
    const int grow = tid >> 2;        // 0..63
    const int gc4  = (tid & 3) * 4;   // 0,4,8,12

    float acc[4][4][4];
    #pragma unroll
    for (int mi = 0; mi < 4; mi++)
        #pragma unroll
        for (int ni = 0; ni < 4; ni++)
            #pragma unroll
            for (int r = 0; r < 4; r++) acc[mi][ni][r] = 0.f;

    for (int k0 = 0; k0 < K; k0 += 16) {
        // stage A and B tiles (128 x 16) into SMEM, converting to tf32 (rna)
        #pragma unroll
        for (int p = 0; p < 2; p++) {
            const int r = grow + p * 64;
            const float4 va = *(const float4*)(A + (size_t)(rowBlock + r) * lda + k0 + gc4);
            uint4 ua = make_uint4(f2tf32(va.x), f2tf32(va.y), f2tf32(va.z), f2tf32(va.w));
            *(uint4*)&As[r * SMS + gc4] = ua;
            const float4 vb = *(const float4*)(Bt + (size_t)(colBlock + r) * ldb + k0 + gc4);
            uint4 ub = make_uint4(f2tf32(vb.x), f2tf32(vb.y), f2tf32(vb.z), f2tf32(vb.w));
            *(uint4*)&Bs[r * SMS + gc4] = ub;
        }
        __syncthreads();

        #pragma unroll
        for (int ks = 0; ks < 2; ks++) {
            const int kk = ks * 8;
            uint32_t af[4][4];
            #pragma unroll
            for (int mi = 0; mi < 4; mi++) {
                const int base = (wm + mi * 16 + gid) * SMS + kk;
                af[mi][0] = As[base + tg];
                af[mi][1] = As[base + 8 * SMS + tg];
                af[mi][2] = As[base + tg + 4];
                af[mi][3] = As[base + 8 * SMS + tg + 4];
            }
            uint32_t bf[4][2];
            #pragma unroll
            for (int ni = 0; ni < 4; ni++) {
                const int base = (wn + ni * 8 + gid) * SMS + kk;
                bf[ni][0] = Bs[base + tg];
                bf[ni][1] = Bs[base + tg + 4];
            }
            #pragma unroll
            for (int mi = 0; mi < 4; mi++)
                #pragma unroll
                for (int ni = 0; ni < 4; ni++)
                    mma_tf32(acc[mi][ni], af[mi], bf[ni]);
        }
        __syncthreads();
    }

    // epilogue: c0,c1 -> (row, 2tg..2tg+1); c2,c3 -> (row+8, same cols)
    #pragma unroll
    for (int mi = 0; mi < 4; mi++) {
        #pragma unroll
        for (int half = 0; half < 2; half++) {
            const size_t r = (size_t)(rowBlock + wm + mi * 16 + gid + half * 8);
            #pragma unroll
            for (int ni = 0; ni < 4; ni++) {
                const size_t c = (size_t)(colBlock + wn + ni * 8 + 2 * tg);
                float2 o;
                o.x = acc[mi][ni][half * 2 + 0] * alpha;
                o.y = acc[mi][ni][half * 2 + 1] * alpha;
                if (BIAS) {
                    const float2 bb = *(const float2*)(bias + c);
                    o.x += bb.x; o.y += bb.y;
                }
                if (RES) {
                    const float2 rr = *(const float2*)(resz + r * ldc + c);
                    o.x += rr.x; o.y += rr.y;
                }
                *(float2*)(Cm + r * ldc + c) = o;
            }
        }
    }
}

// ---------------------------------------------------------------------------
// Row softmax (in-place)
// ---------------------------------------------------------------------------
__global__ void softmax_kernel(float* __restrict__ S) {
    __shared__ float sh[8];
    const size_t row = blockIdx.x;
    float* p = S + row * 4096;
    const int tid = threadIdx.x;
    float4 v[4];
    float mx = -1e30f;
    #pragma unroll
    for (int i = 0; i < 4; i++) {
        v[i] = ((const float4*)p)[tid + i*256];
        mx = fmaxf(mx, fmaxf(fmaxf(v[i].x, v[i].y), fmaxf(v[i].z, v[i].w)));
    }
    #pragma unroll
    for (int o = 16; o; o >>= 1) mx = fmaxf(mx, __shfl_xor_sync(0xffffffffu, mx, o));
    if ((tid & 31) == 0) sh[tid >> 5] = mx;
    __syncthreads();
    mx = sh[0];
    #pragma unroll
    for (int w = 1; w < 8; w++) mx = fmaxf(mx, sh[w]);

    float sum = 0.f;
    #pragma unroll
    for (int i = 0; i < 4; i++) {
        v[i].x = expf(v[i].x - mx); v[i].y = expf(v[i].y - mx);
        v[i].z = expf(v[i].z - mx); v[i].w = expf(v[i].w - mx);
        sum += v[i].x + v[i].y + v[i].z + v[i].w;
    }
    #pragma unroll
    for (int o = 16; o; o >>= 1) sum += __shfl_xor_sync(0xffffffffu, sum, o);
    __syncthreads();
    if ((tid & 31) == 0) sh[tid >> 5] = sum;
    __syncthreads();
    sum = 0.f;
    #pragma unroll
    for (int w = 0; w < 8; w++) sum += sh[w];
    const float inv = 1.f / sum;
    #pragma unroll
    for (int i = 0; i < 4; i++) {
        v[i].x *= inv; v[i].y *= inv; v[i].z *= inv; v[i].w *= inv;
        ((float4*)p)[tid + i*256] = v[i];
    }
}

// ---------------------------------------------------------------------------
// launch
// ---------------------------------------------------------------------------
extern "C" void kernel_launch(void* const* d_in, const int* in_sizes, int n_in,
                              void* d_out, int out_size) {
    const float* x     = (const float*)d_in[0];
    const float* gamma = (const float*)d_in[1];
    const float* beta  = (const float*)d_in[2];
    const float* wq    = (const float*)d_in[3];
    const float* bq    = (const float*)d_in[4];
    const float* wk    = (const float*)d_in[5];
    const float* bk    = (const float*)d_in[6];
    const float* wv    = (const float*)d_in[7];
    const float* bv    = (const float*)d_in[8];
    const float* wp    = (const float*)d_in[9];
    const float* bp    = (const float*)d_in[10];
    float* out = (float*)d_out;

    float *xn, *qkv, *attn, *vt, *wt, *mean, *rstd;
    cudaGetSymbolAddress((void**)&xn,   g_xn);
    cudaGetSymbolAddress((void**)&qkv,  g_qkv);
    cudaGetSymbolAddress((void**)&attn, g_attn);
    cudaGetSymbolAddress((void**)&vt,   g_vt);
    cudaGetSymbolAddress((void**)&wt,   g_wt);
    cudaGetSymbolAddress((void**)&mean, g_mean);
    cudaGetSymbolAddress((void**)&rstd, g_rstd);
    float* q  = qkv;
    float* k  = qkv + (size_t)NBROWS*CD;
    float* v  = qkv + (size_t)2*NBROWS*CD;
    float* ao = xn;   // alias: xn dead after QKV projections
    float* wqT = wt;
    float* wkT = wt + (size_t)CD*CD;
    float* wvT = wt + (size_t)2*CD*CD;
    float* wpT = wt + (size_t)3*CD*CD;

    // 1) GroupNorm
    gn_stats<<<BSZ*NGROUPS, 256>>>(x, mean, rstd);
    gn_norm<<<(NBROWS*CD/4)/256, 256>>>(x, gamma, beta, mean, rstd, xn);

    // 2) weight transposes ([K,N] -> [N,K] so all GEMMs are NT)
    {
        dim3 b(32, 8), g(CD/32, CD/32, 1);
        transpose_kernel<<<g, b>>>(wq, wqT, CD, CD, 0, 0);
        transpose_kernel<<<g, b>>>(wk, wkT, CD, CD, 0, 0);
        transpose_kernel<<<g, b>>>(wv, wvT, CD, CD, 0, 0);
        transpose_kernel<<<g, b>>>(wp, wpT, CD, CD, 0, 0);
    }

    // 3) q, k, v projections: [8192,512] x [512,512]^T
    {
        dim3 g(CD/128, NBROWS/128, 1);
        gemm_mma<true, false><<<g, 256>>>(xn, wqT, bq, nullptr, q, CD, CD, CD, CD, 1.f, 0, 0, 0);
        gemm_mma<true, false><<<g, 256>>>(xn, wkT, bk, nullptr, k, CD, CD, CD, CD, 1.f, 0, 0, 0);
        gemm_mma<true, false><<<g, 256>>>(xn, wvT, bv, nullptr, v, CD, CD, CD, CD, 1.f, 0, 0, 0);
    }

    // 4) v transpose per batch: [4096,512] -> [512,4096]
    {
        dim3 b(32, 8), g(CD/32, HWN/32, BSZ);
        transpose_kernel<<<g, b>>>(v, vt, HWN, CD, (size_t)HWN*CD, (size_t)CD*HWN);
    }

    // 5) scores = q k^T * 1/sqrt(C)  (NT: both K-major), batches via z
    const float scale = 0.044194173824159216f;
    {
        dim3 g(HWN/128, HWN/128, BSZ);
        gemm_mma<false, false><<<g, 256>>>(q, k, nullptr, nullptr, attn,
                                           CD, CD, CD, HWN, scale,
                                           (size_t)HWN*CD, (size_t)HWN*CD, (size_t)HWN*HWN);
    }

    // 6) softmax rows (in place)
    softmax_kernel<<<NBROWS, 256>>>(attn);

    // 7) ao = attn @ v  (NT with vT: K=4096), batches via z
    {
        dim3 g(CD/128, HWN/128, BSZ);
        gemm_mma<false, false><<<g, 256>>>(attn, vt, nullptr, nullptr, ao,
                                           HWN, HWN, HWN, CD, 1.f,
                                           (size_t)HWN*HWN, (size_t)CD*HWN, (size_t)HWN*CD);
    }

    // 8) final projection + bias + residual -> d_out
    {
        dim3 g(CD/128, NBROWS/128, 1);
        gemm_mma<true, true><<<g, 256>>>(ao, wpT, bp, x, out, CD, CD, CD, CD, 1.f, 0, 0, 0);
    }
}

// round 8
// speedup vs baseline: 2.6042x; 1.0365x over previous
#include <cuda_runtime.h>
#include <math.h>
#include <stdint.h>

// Problem constants (fixed shapes)
#define BSZ 2
#define HWN 4096
#define CD  512
#define NBROWS (BSZ*HWN)      // 8192
#define NGROUPS 32

// ---------------------------------------------------------------------------
// Scratch (device globals; no allocations)
// ---------------------------------------------------------------------------
__device__ float g_xn  [(size_t)NBROWS*CD];           // xn; later reused as "ao"
__device__ float g_qkv [(size_t)3*NBROWS*CD];         // q | k | v
__device__ float g_attn[(size_t)BSZ*HWN*HWN];         // 134 MB
__device__ float g_vt  [(size_t)BSZ*CD*HWN];          // v transposed per batch
__device__ float g_wt  [(size_t)4*CD*CD];             // wq^T | wk^T | wv^T | wp^T
__device__ float g_mean[BSZ*NGROUPS];
__device__ float g_rstd[BSZ*NGROUPS];

// ---------------------------------------------------------------------------
// tf32 helpers (portable sm_80+ path; NO 'a'-suffix features)
// ---------------------------------------------------------------------------
__device__ __forceinline__ uint32_t f2tf32(float f) {
    uint32_t u;
    asm("cvt.rna.tf32.f32 %0, %1;" : "=r"(u) : "f"(f));
    return u;
}
__device__ __forceinline__ uint4 cvt4(float4 v) {
    return make_uint4(f2tf32(v.x), f2tf32(v.y), f2tf32(v.z), f2tf32(v.w));
}
__device__ __forceinline__ void mma_tf32(float c[4], const uint32_t a[4], const uint32_t b[2]) {
    asm volatile(
        "mma.sync.aligned.m16n8k8.row.col.f32.tf32.tf32.f32 "
        "{%0,%1,%2,%3}, {%4,%5,%6,%7}, {%8,%9}, {%0,%1,%2,%3};"
        : "+f"(c[0]), "+f"(c[1]), "+f"(c[2]), "+f"(c[3])
        : "r"(a[0]), "r"(a[1]), "r"(a[2]), "r"(a[3]), "r"(b[0]), "r"(b[1]));
}

// ---------------------------------------------------------------------------
// GroupNorm
// ---------------------------------------------------------------------------
__global__ void gn_stats(const float* __restrict__ x,
                         float* __restrict__ mean, float* __restrict__ rstd) {
    __shared__ float shs[8], shss[8];
    const int bg = blockIdx.x;
    const int b = bg >> 5, g = bg & 31;
    const float4* xb = (const float4*)x + (size_t)b*524288 + g*4;
    float s = 0.f, ss = 0.f;
    for (int i = threadIdx.x; i < 16384; i += 256) {
        int n = i >> 2, j = i & 3;
        float4 vv = xb[(size_t)n*128 + j];
        s  += vv.x + vv.y + vv.z + vv.w;
        ss += vv.x*vv.x + vv.y*vv.y + vv.z*vv.z + vv.w*vv.w;
    }
    #pragma unroll
    for (int o = 16; o; o >>= 1) {
        s  += __shfl_xor_sync(0xffffffffu, s,  o);
        ss += __shfl_xor_sync(0xffffffffu, ss, o);
    }
    if ((threadIdx.x & 31) == 0) { shs[threadIdx.x>>5] = s; shss[threadIdx.x>>5] = ss; }
    __syncthreads();
    if (threadIdx.x == 0) {
        s = 0.f; ss = 0.f;
        #pragma unroll
        for (int w = 0; w < 8; w++) { s += shs[w]; ss += shss[w]; }
        float m   = s * (1.f/65536.f);
        float var = ss * (1.f/65536.f) - m*m;
        mean[bg] = m;
        rstd[bg] = rsqrtf(var + 1e-5f);
    }
}

__global__ void gn_norm(const float* __restrict__ x,
                        const float* __restrict__ gamma, const float* __restrict__ beta,
                        const float* __restrict__ mean, const float* __restrict__ rstd,
                        float* __restrict__ xn) {
    const int idx = blockIdx.x * blockDim.x + threadIdx.x;
    float4 v = ((const float4*)x)[idx];
    const int c4 = idx & 127;
    const int b  = idx >> 19;
    const int g  = c4 >> 2;
    const int bg = b * 32 + g;
    const float m = mean[bg], r = rstd[bg];
    const float4 ga = ((const float4*)gamma)[c4];
    const float4 be = ((const float4*)beta)[c4];
    float4 o;
    o.x = (v.x - m) * r * ga.x + be.x;
    o.y = (v.y - m) * r * ga.y + be.y;
    o.z = (v.z - m) * r * ga.z + be.z;
    o.w = (v.w - m) * r * ga.w + be.w;
    ((float4*)xn)[idx] = o;
}

// ---------------------------------------------------------------------------
// Tiled transpose: out[c][r] = in[r][c].  block (32,8), grid (cols/32, rows/32, nz)
// ---------------------------------------------------------------------------
__global__ void transpose_kernel(const float* __restrict__ in, float* __restrict__ out,
                                 int rows, int cols, size_t zInStride, size_t zOutStride) {
    __shared__ float t[32][33];
    const float* inz = in + blockIdx.z * zInStride;
    float* outz = out + blockIdx.z * zOutStride;
    int c0 = blockIdx.x * 32, r0 = blockIdx.y * 32;
    int x = threadIdx.x;
    #pragma unroll
    for (int y = threadIdx.y; y < 32; y += 8)
        t[y][x] = inz[(size_t)(r0 + y) * cols + c0 + x];
    __syncthreads();
    #pragma unroll
    for (int y = threadIdx.y; y < 32; y += 8)
        outz[(size_t)(c0 + y) * rows + r0 + x] = t[x][y];
}

// ---------------------------------------------------------------------------
// Tensor-core tf32 NT GEMM (software-pipelined, double-buffered SMEM):
//   Cm[m][n] = alpha * sum_k A[m][k] * Bt[n][k]  (+bias[n]) (+res[m][n])
// CTA tile 128x128, BK=16, 256 threads = 8 warps in 2(m) x 4(n), warp tile 64x32.
// SMEM k-major with +4 float pad (stride 20) -> conflict-free fragment loads.
// blockIdx.z selects batch via zA/zB/zC element strides.
// ---------------------------------------------------------------------------
#define SMS 20   // smem row stride in 32-bit words

template<bool BIAS, bool RES>
__global__ __launch_bounds__(256)
void gemm_mma(const float* __restrict__ A, const float* __restrict__ Bt,
              const float* __restrict__ bias, const float* __restrict__ res,
              float* __restrict__ Cm,
              int K, int lda, int ldb, int ldc, float alpha,
              size_t zA, size_t zB, size_t zC) {
    __shared__ uint32_t As[2][128 * SMS];
    __shared__ uint32_t Bs[2][128 * SMS];

    A  += blockIdx.z * zA;
    Bt += blockIdx.z * zB;
    Cm += blockIdx.z * zC;
    const float* resz = RES ? (res + blockIdx.z * zC) : res;

    const int tid = threadIdx.x;
    const int wid = tid >> 5;
    const int lane = tid & 31;
    const int gid = lane >> 2;        // 0..7
    const int tg  = lane & 3;         // 0..3
    const int wm = (wid & 1) * 64;    // warp m offset
    const int wn = (wid >> 1) * 32;   // warp n offset
    const int rowBlock = blockIdx.y * 128;
    const int colBlock = blockIdx.x * 128;

    // staging coords: each thread owns rows {grow, grow+64}, 4 k-cols at gc4
    const int grow = tid >> 2;        // 0..63
    const int gc4  = (tid & 3) * 4;   // 0,4,8,12

    const float* Ap0 = A  + (size_t)(rowBlock + grow)      * lda + gc4;
    const float* Ap1 = A  + (size_t)(rowBlock + grow + 64) * lda + gc4;
    const float* Bp0 = Bt + (size_t)(colBlock + grow)      * ldb + gc4;
    const float* Bp1 = Bt + (size_t)(colBlock + grow + 64) * ldb + gc4;

    float acc[4][4][4];
    #pragma unroll
    for (int mi = 0; mi < 4; mi++)
        #pragma unroll
        for (int ni = 0; ni < 4; ni++)
            #pragma unroll
            for (int r = 0; r < 4; r++) acc[mi][ni][r] = 0.f;

    float4 pa0, pa1, pb0, pb1;

    // prologue: load + store tile 0
    pa0 = *(const float4*)(Ap0);
    pa1 = *(const float4*)(Ap1);
    pb0 = *(const float4*)(Bp0);
    pb1 = *(const float4*)(Bp1);
    *(uint4*)&As[0][grow * SMS + gc4]        = cvt4(pa0);
    *(uint4*)&As[0][(grow + 64) * SMS + gc4] = cvt4(pa1);
    *(uint4*)&Bs[0][grow * SMS + gc4]        = cvt4(pb0);
    *(uint4*)&Bs[0][(grow + 64) * SMS + gc4] = cvt4(pb1);
    __syncthreads();

    const int T = K >> 4;
    int p = 0;
    for (int t = 0; t < T; t++) {
        // prefetch next tile into registers (overlaps with MMAs below)
        if (t + 1 < T) {
            const int kn = (t + 1) << 4;
            pa0 = *(const float4*)(Ap0 + kn);
            pa1 = *(const float4*)(Ap1 + kn);
            pb0 = *(const float4*)(Bp0 + kn);
            pb1 = *(const float4*)(Bp1 + kn);
        }

        // compute current tile from SMEM buffer p
        const uint32_t* Ab = As[p];
        const uint32_t* Bb = Bs[p];
        #pragma unroll
        for (int ks = 0; ks < 2; ks++) {
            const int kk = ks * 8;
            uint32_t af[4][4];
            #pragma unroll
            for (int mi = 0; mi < 4; mi++) {
                const int base = (wm + mi * 16 + gid) * SMS + kk;
                af[mi][0] = Ab[base + tg];
                af[mi][1] = Ab[base + 8 * SMS + tg];
                af[mi][2] = Ab[base + tg + 4];
                af[mi][3] = Ab[base + 8 * SMS + tg + 4];
            }
            uint32_t bf[4][2];
            #pragma unroll
            for (int ni = 0; ni < 4; ni++) {
                const int base = (wn + ni * 8 + gid) * SMS + kk;
                bf[ni][0] = Bb[base + tg];
                bf[ni][1] = Bb[base + tg + 4];
            }
            #pragma unroll
            for (int mi = 0; mi < 4; mi++)
                #pragma unroll
                for (int ni = 0; ni < 4; ni++)
                    mma_tf32(acc[mi][ni], af[mi], bf[ni]);
        }

        // stage next tile into the other buffer; single barrier per iteration
        if (t + 1 < T) {
            const int q = p ^ 1;
            *(uint4*)&As[q][grow * SMS + gc4]        = cvt4(pa0);
            *(uint4*)&As[q][(grow + 64) * SMS + gc4] = cvt4(pa1);
            *(uint4*)&Bs[q][grow * SMS + gc4]        = cvt4(pb0);
            *(uint4*)&Bs[q][(grow + 64) * SMS + gc4] = cvt4(pb1);
            __syncthreads();
            p = q;
        }
    }

    // epilogue: c0,c1 -> (row, 2tg..2tg+1); c2,c3 -> (row+8, same cols)
    #pragma unroll
    for (int mi = 0; mi < 4; mi++) {
        #pragma unroll
        for (int half = 0; half < 2; half++) {
            const size_t r = (size_t)(rowBlock + wm + mi * 16 + gid + half * 8);
            #pragma unroll
            for (int ni = 0; ni < 4; ni++) {
                const size_t c = (size_t)(colBlock + wn + ni * 8 + 2 * tg);
                float2 o;
                o.x = acc[mi][ni][half * 2 + 0] * alpha;
                o.y = acc[mi][ni][half * 2 + 1] * alpha;
                if (BIAS) {
                    const float2 bb = *(const float2*)(bias + c);
                    o.x += bb.x; o.y += bb.y;
                }
                if (RES) {
                    const float2 rr = *(const float2*)(resz + r * ldc + c);
                    o.x += rr.x; o.y += rr.y;
                }
                *(float2*)(Cm + r * ldc + c) = o;
            }
        }
    }
}

// ---------------------------------------------------------------------------
// Row softmax (in-place)
// ---------------------------------------------------------------------------
__global__ void softmax_kernel(float* __restrict__ S) {
    __shared__ float sh[8];
    const size_t row = blockIdx.x;
    float* p = S + row * 4096;
    const int tid = threadIdx.x;
    float4 v[4];
    float mx = -1e30f;
    #pragma unroll
    for (int i = 0; i < 4; i++) {
        v[i] = ((const float4*)p)[tid + i*256];
        mx = fmaxf(mx, fmaxf(fmaxf(v[i].x, v[i].y), fmaxf(v[i].z, v[i].w)));
    }
    #pragma unroll
    for (int o = 16; o; o >>= 1) mx = fmaxf(mx, __shfl_xor_sync(0xffffffffu, mx, o));
    if ((tid & 31) == 0) sh[tid >> 5] = mx;
    __syncthreads();
    mx = sh[0];
    #pragma unroll
    for (int w = 1; w < 8; w++) mx = fmaxf(mx, sh[w]);

    float sum = 0.f;
    #pragma unroll
    for (int i = 0; i < 4; i++) {
        v[i].x = expf(v[i].x - mx); v[i].y = expf(v[i].y - mx);
        v[i].z = expf(v[i].z - mx); v[i].w = expf(v[i].w - mx);
        sum += v[i].x + v[i].y + v[i].z + v[i].w;
    }
    #pragma unroll
    for (int o = 16; o; o >>= 1) sum += __shfl_xor_sync(0xffffffffu, sum, o);
    __syncthreads();
    if ((tid & 31) == 0) sh[tid >> 5] = sum;
    __syncthreads();
    sum = 0.f;
    #pragma unroll
    for (int w = 0; w < 8; w++) sum += sh[w];
    const float inv = 1.f / sum;
    #pragma unroll
    for (int i = 0; i < 4; i++) {
        v[i].x *= inv; v[i].y *= inv; v[i].z *= inv; v[i].w *= inv;
        ((float4*)p)[tid + i*256] = v[i];
    }
}

// ---------------------------------------------------------------------------
// launch
// ---------------------------------------------------------------------------
extern "C" void kernel_launch(void* const* d_in, const int* in_sizes, int n_in,
                              void* d_out, int out_size) {
    const float* x     = (const float*)d_in[0];
    const float* gamma = (const float*)d_in[1];
    const float* beta  = (const float*)d_in[2];
    const float* wq    = (const float*)d_in[3];
    const float* bq    = (const float*)d_in[4];
    const float* wk    = (const float*)d_in[5];
    const float* bk    = (const float*)d_in[6];
    const float* wv    = (const float*)d_in[7];
    const float* bv    = (const float*)d_in[8];
    const float* wp    = (const float*)d_in[9];
    const float* bp    = (const float*)d_in[10];
    float* out = (float*)d_out;

    float *xn, *qkv, *attn, *vt, *wt, *mean, *rstd;
    cudaGetSymbolAddress((void**)&xn,   g_xn);
    cudaGetSymbolAddress((void**)&qkv,  g_qkv);
    cudaGetSymbolAddress((void**)&attn, g_attn);
    cudaGetSymbolAddress((void**)&vt,   g_vt);
    cudaGetSymbolAddress((void**)&wt,   g_wt);
    cudaGetSymbolAddress((void**)&mean, g_mean);
    cudaGetSymbolAddress((void**)&rstd, g_rstd);
    float* q  = qkv;
    float* k  = qkv + (size_t)NBROWS*CD;
    float* v  = qkv + (size_t)2*NBROWS*CD;
    float* ao = xn;   // alias: xn dead after QKV projections
    float* wqT = wt;
    float* wkT = wt + (size_t)CD*CD;
    float* wvT = wt + (size_t)2*CD*CD;
    float* wpT = wt + (size_t)3*CD*CD;

    // 1) GroupNorm
    gn_stats<<<BSZ*NGROUPS, 256>>>(x, mean, rstd);
    gn_norm<<<(NBROWS*CD/4)/256, 256>>>(x, gamma, beta, mean, rstd, xn);

    // 2) weight transposes ([K,N] -> [N,K] so all GEMMs are NT)
    {
        dim3 b(32, 8), g(CD/32, CD/32, 1);
        transpose_kernel<<<g, b>>>(wq, wqT, CD, CD, 0, 0);
        transpose_kernel<<<g, b>>>(wk, wkT, CD, CD, 0, 0);
        transpose_kernel<<<g, b>>>(wv, wvT, CD, CD, 0, 0);
        transpose_kernel<<<g, b>>>(wp, wpT, CD, CD, 0, 0);
    }

    // 3) q, k, v projections: [8192,512] x [512,512]^T
    {
        dim3 g(CD/128, NBROWS/128, 1);
        gemm_mma<true, false><<<g, 256>>>(xn, wqT, bq, nullptr, q, CD, CD, CD, CD, 1.f, 0, 0, 0);
        gemm_mma<true, false><<<g, 256>>>(xn, wkT, bk, nullptr, k, CD, CD, CD, CD, 1.f, 0, 0, 0);
        gemm_mma<true, false><<<g, 256>>>(xn, wvT, bv, nullptr, v, CD, CD, CD, CD, 1.f, 0, 0, 0);
    }

    // 4) v transpose per batch: [4096,512] -> [512,4096]
    {
        dim3 b(32, 8), g(CD/32, HWN/32, BSZ);
        transpose_kernel<<<g, b>>>(v, vt, HWN, CD, (size_t)HWN*CD, (size_t)CD*HWN);
    }

    // 5) scores = q k^T * 1/sqrt(C)  (NT: both K-major), batches via z
    const float scale = 0.044194173824159216f;
    {
        dim3 g(HWN/128, HWN/128, BSZ);
        gemm_mma<false, false><<<g, 256>>>(q, k, nullptr, nullptr, attn,
                                           CD, CD, CD, HWN, scale,
                                           (size_t)HWN*CD, (size_t)HWN*CD, (size_t)HWN*HWN);
    }

    // 6) softmax rows (in place)
    softmax_kernel<<<NBROWS, 256>>>(attn);

    // 7) ao = attn @ v  (NT with vT: K=4096), batches via z
    {
        dim3 g(CD/128, HWN/128, BSZ);
        gemm_mma<false, false><<<g, 256>>>(attn, vt, nullptr, nullptr, ao,
                                           HWN, HWN, HWN, CD, 1.f,
                                           (size_t)HWN*HWN, (size_t)CD*HWN, (size_t)HWN*CD);
    }

    // 8) final projection + bias + residual -> d_out
    {
        dim3 g(CD/128, NBROWS/128, 1);
        gemm_mma<true, true><<<g, 256>>>(ao, wpT, bp, x, out, CD, CD, CD, CD, 1.f, 0, 0, 0);
    }
}